// round 2
// baseline (speedup 1.0000x reference)
#include <cuda_runtime.h>

#define Bb_  16
#define N1_  4096
#define N2_  1024
#define C1_  128
#define C2_  256
#define K0_  384   // C1+C2
#define M0_  256   // layer0 out channels
#define M1_  128   // layer1 out channels
#define KNN_ 3
#define EPSD 1e-10f
#define BNEPS 1e-5f

// ---------------- scratch (device globals; no runtime allocation) ------------
__device__ int   g_idx[Bb_ * N1_ * KNN_];
__device__ float g_w  [Bb_ * N1_ * KNN_];
__device__ float g_interp[(size_t)Bb_ * C2_ * N1_];   // 67 MB
__device__ float g_y0    [(size_t)Bb_ * M0_ * N1_];   // 67 MB
__device__ float g_scale0[M0_], g_shift0[M0_];
__device__ float g_scale1[M1_], g_shift1[M1_];

// ---------------- kernel 1: 3-NN + inverse-distance weights -----------------
__global__ void __launch_bounds__(256) knn_kernel(const float* __restrict__ xyz1,
                                                  const float* __restrict__ xyz2)
{
    __shared__ float sx[N2_], sy[N2_], sz[N2_], ss[N2_];
    const int b = blockIdx.y;
    const float* p2 = xyz2 + (size_t)b * N2_ * 3;
    for (int j = threadIdx.x; j < N2_; j += blockDim.x) {
        float x = p2[j*3+0], y = p2[j*3+1], z = p2[j*3+2];
        sx[j] = x; sy[j] = y; sz[j] = z; ss[j] = x*x + y*y + z*z;
    }
    __syncthreads();

    const int n = blockIdx.x * blockDim.x + threadIdx.x;
    const float* p1 = xyz1 + ((size_t)b * N1_ + n) * 3;
    const float x1 = p1[0], y1 = p1[1], z1 = p1[2];
    const float s1 = x1*x1 + y1*y1 + z1*z1;

    float d0 = 3.0e38f, d1 = 3.0e38f, d2 = 3.0e38f;
    int   i0 = 0, i1 = 0, i2 = 0;
    #pragma unroll 4
    for (int j = 0; j < N2_; j++) {
        float d = s1 + ss[j] - 2.0f * (x1*sx[j] + y1*sy[j] + z1*sz[j]);
        d = fmaxf(d, EPSD);
        // strict < keeps earlier index on ties (matches top_k tie-break)
        if (d < d2) {
            if (d < d1) {
                d2 = d1; i2 = i1;
                if (d < d0) { d1 = d0; i1 = i0; d0 = d; i0 = j; }
                else        { d1 = d;  i1 = j; }
            } else { d2 = d; i2 = j; }
        }
    }
    float w0 = 1.0f/d0, w1 = 1.0f/d1, w2 = 1.0f/d2;
    float inv = 1.0f / (w0 + w1 + w2);
    size_t base = ((size_t)b * N1_ + n) * KNN_;
    g_idx[base+0] = i0; g_idx[base+1] = i1; g_idx[base+2] = i2;
    g_w  [base+0] = w0*inv; g_w[base+1] = w1*inv; g_w[base+2] = w2*inv;
}

// ---------------- kernel 2: interpolate points2 -> g_interp ------------------
__global__ void __launch_bounds__(256) interp_kernel(const float* __restrict__ points2)
{
    const size_t total = (size_t)Bb_ * C2_ * N1_;
    size_t i = (size_t)blockIdx.x * blockDim.x + threadIdx.x;
    if (i >= total) return;
    const int n = (int)(i % N1_);
    const int c = (int)((i / N1_) % C2_);
    const int b = (int)(i / ((size_t)N1_ * C2_));
    const size_t kb = ((size_t)b * N1_ + n) * KNN_;
    const int   j0 = g_idx[kb+0], j1 = g_idx[kb+1], j2 = g_idx[kb+2];
    const float w0 = g_w[kb+0],  w1 = g_w[kb+1],  w2 = g_w[kb+2];
    const float* p = points2 + ((size_t)b * C2_ + c) * N2_;
    g_interp[i] = w0*p[j0] + w1*p[j1] + w2*p[j2];
}

// ---------------- kernel 3: SGEMM + bias (128x128x8 tile, 8x8 micro) --------
// Y[b, m, n] = sum_k W[m,k] * X[b,k,n] + bias[m]
// X rows [0,KA) come from XA (batch stride KA*N1), rows [KA,Kdim) from XB.
__global__ void __launch_bounds__(256) gemm_bias_kernel(
    const float* __restrict__ Wm, int Mdim, int Kdim,
    const float* __restrict__ XA, int KA,
    const float* __restrict__ XB,
    const float* __restrict__ bias,
    float* __restrict__ Y)
{
    __shared__ float As[8][128];
    __shared__ float Bs[8][128];

    const int b  = blockIdx.z;
    const int n0 = blockIdx.x * 128;
    const int m0 = blockIdx.y * 128;
    const int tid = threadIdx.x;
    const int tx = tid & 15;        // n-frag
    const int ty = tid >> 4;        // m-frag

    const float* Abat = XA + (size_t)b * KA * N1_;
    const float* Bbat = XB + (size_t)b * (Kdim - KA) * N1_;

    // load indices
    const int wr = tid >> 1;            // 0..127  W row
    const int wk = (tid & 1) * 4;       // 0 or 4  W col group
    const int xr = tid >> 5;            // 0..7    X row
    const int xc = (tid & 31) * 4;      // X col group

    float acc[8][8];
    #pragma unroll
    for (int i = 0; i < 8; i++)
        #pragma unroll
        for (int j = 0; j < 8; j++) acc[i][j] = 0.0f;

    for (int kt = 0; kt < Kdim; kt += 8) {
        {
            const float4 wv = *(const float4*)(Wm + (size_t)(m0 + wr) * Kdim + kt + wk);
            As[wk+0][wr] = wv.x; As[wk+1][wr] = wv.y;
            As[wk+2][wr] = wv.z; As[wk+3][wr] = wv.w;
        }
        {
            const int k = kt + xr;
            const float* src = (k < KA) ? (Abat + (size_t)k * N1_)
                                        : (Bbat + (size_t)(k - KA) * N1_);
            *(float4*)&Bs[xr][xc] = *(const float4*)(src + n0 + xc);
        }
        __syncthreads();

        #pragma unroll
        for (int kk = 0; kk < 8; kk++) {
            float a[8], bf[8];
            *(float4*)(a)     = *(const float4*)&As[kk][ty*8];
            *(float4*)(a + 4) = *(const float4*)&As[kk][ty*8 + 4];
            *(float4*)(bf)    = *(const float4*)&Bs[kk][tx*8];
            *(float4*)(bf + 4)= *(const float4*)&Bs[kk][tx*8 + 4];
            #pragma unroll
            for (int i = 0; i < 8; i++)
                #pragma unroll
                for (int j = 0; j < 8; j++)
                    acc[i][j] = fmaf(a[i], bf[j], acc[i][j]);
        }
        __syncthreads();
    }

    #pragma unroll
    for (int i = 0; i < 8; i++) {
        const int m = m0 + ty*8 + i;
        const float bv = bias[m];
        float* dst = Y + ((size_t)b * Mdim + m) * N1_ + n0 + tx*8;
        float4 v0 = make_float4(acc[i][0]+bv, acc[i][1]+bv, acc[i][2]+bv, acc[i][3]+bv);
        float4 v1 = make_float4(acc[i][4]+bv, acc[i][5]+bv, acc[i][6]+bv, acc[i][7]+bv);
        *(float4*)(dst)     = v0;
        *(float4*)(dst + 4) = v1;
    }
}

// ---------------- kernel 4: per-channel batch stats -> scale/shift ----------
__global__ void __launch_bounds__(256) stats_kernel(const float* __restrict__ Yv, int Mdim,
                                                    const float* __restrict__ gamma,
                                                    const float* __restrict__ beta,
                                                    int layer)
{
    const int c = blockIdx.x;
    float s = 0.0f, s2 = 0.0f;
    for (int b = 0; b < Bb_; b++) {
        const float* p = Yv + ((size_t)b * Mdim + c) * N1_;
        for (int n = threadIdx.x * 4; n < N1_; n += blockDim.x * 4) {
            float4 v = *(const float4*)(p + n);
            s  += v.x + v.y + v.z + v.w;
            s2 += v.x*v.x + v.y*v.y + v.z*v.z + v.w*v.w;
        }
    }
    __shared__ float sh[256], sh2[256];
    sh[threadIdx.x] = s; sh2[threadIdx.x] = s2;
    __syncthreads();
    for (int o = 128; o > 0; o >>= 1) {
        if (threadIdx.x < o) {
            sh[threadIdx.x]  += sh[threadIdx.x + o];
            sh2[threadIdx.x] += sh2[threadIdx.x + o];
        }
        __syncthreads();
    }
    if (threadIdx.x == 0) {
        const float cnt = (float)(Bb_ * N1_);
        float m = sh[0] / cnt;
        float v = sh2[0] / cnt - m * m;
        float r = rsqrtf(v + BNEPS);
        float a = gamma[c] * r;
        if (layer == 0) { g_scale0[c] = a; g_shift0[c] = beta[c] - a * m; }
        else            { g_scale1[c] = a; g_shift1[c] = beta[c] - a * m; }
    }
}

// ---------------- kernel 5: fused BN(affine) + ReLU, in place ----------------
__global__ void __launch_bounds__(256) bnrelu_kernel(float* __restrict__ Yv, int Mdim, int layer)
{
    const size_t total4 = (size_t)Bb_ * Mdim * N1_ / 4;
    const size_t i = (size_t)blockIdx.x * blockDim.x + threadIdx.x;
    if (i >= total4) return;
    const int c = (int)((i >> 10) % Mdim);   // N1_/4 = 1024 float4 per row
    const float a  = (layer == 0) ? g_scale0[c] : g_scale1[c];
    const float sh = (layer == 0) ? g_shift0[c] : g_shift1[c];
    float4 v = ((float4*)Yv)[i];
    v.x = fmaxf(fmaf(a, v.x, sh), 0.0f);
    v.y = fmaxf(fmaf(a, v.y, sh), 0.0f);
    v.z = fmaxf(fmaf(a, v.z, sh), 0.0f);
    v.w = fmaxf(fmaf(a, v.w, sh), 0.0f);
    ((float4*)Yv)[i] = v;
}

// ---------------- launch ------------------------------------------------------
extern "C" void kernel_launch(void* const* d_in, const int* in_sizes, int n_in,
                              void* d_out, int out_size)
{
    const float* xyz1    = (const float*)d_in[0];
    const float* xyz2    = (const float*)d_in[1];
    const float* points1 = (const float*)d_in[2];
    const float* points2 = (const float*)d_in[3];
    const float* W0 = (const float*)d_in[4];
    const float* b0 = (const float*)d_in[5];
    const float* g0 = (const float*)d_in[6];
    const float* be0= (const float*)d_in[7];
    const float* W1 = (const float*)d_in[8];
    const float* b1 = (const float*)d_in[9];
    const float* g1 = (const float*)d_in[10];
    const float* be1= (const float*)d_in[11];
    float* out = (float*)d_out;

    void* p_interp; cudaGetSymbolAddress(&p_interp, g_interp);
    void* p_y0;     cudaGetSymbolAddress(&p_y0, g_y0);
    float* interp = (float*)p_interp;
    float* y0     = (float*)p_y0;

    // 1. 3-NN
    knn_kernel<<<dim3(N1_/256, Bb_), 256>>>(xyz1, xyz2);

    // 2. interpolation
    {
        size_t total = (size_t)Bb_ * C2_ * N1_;
        interp_kernel<<<(unsigned)((total + 255) / 256), 256>>>(points2);
    }

    // 3. GEMM0: [256 x 384] x [384 x (B*4096)] + b0 -> y0
    gemm_bias_kernel<<<dim3(N1_/128, M0_/128, Bb_), 256>>>(
        W0, M0_, K0_, points1, C1_, interp, b0, y0);

    // 4. BN stats layer 0
    stats_kernel<<<M0_, 256>>>(y0, M0_, g0, be0, 0);

    // 5. BN+ReLU layer 0 (in place)
    {
        size_t total4 = (size_t)Bb_ * M0_ * N1_ / 4;
        bnrelu_kernel<<<(unsigned)((total4 + 255) / 256), 256>>>(y0, M0_, 0);
    }

    // 6. GEMM1: [128 x 256] x [256 x (B*4096)] + b1 -> out
    gemm_bias_kernel<<<dim3(N1_/128, M1_/128, Bb_), 256>>>(
        W1, M1_, M0_, y0, M0_, y0 /*unused*/, b1, out);

    // 7. BN stats layer 1
    stats_kernel<<<M1_, 256>>>(out, M1_, g1, be1, 1);

    // 8. BN+ReLU layer 1 (in place)
    {
        size_t total4 = (size_t)Bb_ * M1_ * N1_ / 4;
        bnrelu_kernel<<<(unsigned)((total4 + 255) / 256), 256>>>(out, M1_, 1);
    }
}

// round 3
// speedup vs baseline: 1.0589x; 1.0589x over previous
#include <cuda_runtime.h>

#define Bb_  16
#define N1_  4096
#define N2_  1024
#define C1_  128
#define C2_  256
#define K0_  384   // C1+C2
#define M0_  256
#define M1_  128
#define KNN_ 3
#define EPSD 1e-10f
#define BNEPS 1e-5f

typedef unsigned long long ull;

// ---------------- packed fp32x2 helpers (sm_103a FFMA2 path) -----------------
__device__ __forceinline__ ull pack2(float lo, float hi) {
    ull r; asm("mov.b64 %0, {%1, %2};" : "=l"(r) : "f"(lo), "f"(hi)); return r;
}
__device__ __forceinline__ void unpack2(ull v, float& lo, float& hi) {
    asm("mov.b64 {%0, %1}, %2;" : "=f"(lo), "=f"(hi) : "l"(v));
}
__device__ __forceinline__ void fma2(ull& acc, ull a, ull b) {
    asm("fma.rn.f32x2 %0, %1, %2, %0;" : "+l"(acc) : "l"(a), "l"(b));
}
__device__ __forceinline__ ull add2(ull a, ull b) {
    ull r; asm("add.rn.f32x2 %0, %1, %2;" : "=l"(r) : "l"(a), "l"(b)); return r;
}

// ---------------- scratch ----------------------------------------------------
__device__ int   g_idx[Bb_ * N1_ * KNN_];
__device__ float g_w  [Bb_ * N1_ * KNN_];
__device__ float g_interp[(size_t)Bb_ * C2_ * N1_];
__device__ float g_y0    [(size_t)Bb_ * M0_ * N1_];
__device__ float g_psum [M0_ * 8];
__device__ float g_psum2[M0_ * 8];
__device__ float g_scale0[M0_], g_shift0[M0_];
__device__ float g_scale1[M1_], g_shift1[M1_];

// ---------------- kernel 1: 3-NN + inverse-distance weights -----------------
__global__ void __launch_bounds__(128) knn_kernel(const float* __restrict__ xyz1,
                                                  const float* __restrict__ xyz2)
{
    __shared__ float sx[N2_], sy[N2_], sz[N2_], ss[N2_];
    const int b = blockIdx.y;
    const float* p2 = xyz2 + (size_t)b * N2_ * 3;
    for (int j = threadIdx.x; j < N2_; j += blockDim.x) {
        float x = p2[j*3+0], y = p2[j*3+1], z = p2[j*3+2];
        sx[j] = x; sy[j] = y; sz[j] = z; ss[j] = x*x + y*y + z*z;
    }
    __syncthreads();

    const int n = blockIdx.x * blockDim.x + threadIdx.x;
    const float* p1 = xyz1 + ((size_t)b * N1_ + n) * 3;
    const float x1 = p1[0], y1 = p1[1], z1 = p1[2];
    const float s1 = x1*x1 + y1*y1 + z1*z1;

    float d0 = 3.0e38f, d1 = 3.0e38f, d2 = 3.0e38f;
    int   i0 = 0, i1 = 0, i2 = 0;
    #pragma unroll 4
    for (int j = 0; j < N2_; j++) {
        float d = s1 + ss[j] - 2.0f * (x1*sx[j] + y1*sy[j] + z1*sz[j]);
        d = fmaxf(d, EPSD);
        if (d < d2) {
            if (d < d1) {
                d2 = d1; i2 = i1;
                if (d < d0) { d1 = d0; i1 = i0; d0 = d; i0 = j; }
                else        { d1 = d;  i1 = j; }
            } else { d2 = d; i2 = j; }
        }
    }
    float w0 = 1.0f/d0, w1 = 1.0f/d1, w2 = 1.0f/d2;
    float inv = 1.0f / (w0 + w1 + w2);
    size_t base = ((size_t)b * N1_ + n) * KNN_;
    g_idx[base+0] = i0; g_idx[base+1] = i1; g_idx[base+2] = i2;
    g_w  [base+0] = w0*inv; g_w[base+1] = w1*inv; g_w[base+2] = w2*inv;
}

// ---------------- kernel 2: interpolate --------------------------------------
__global__ void __launch_bounds__(256) interp_kernel(const float* __restrict__ points2)
{
    const size_t total = (size_t)Bb_ * C2_ * N1_;
    size_t i = (size_t)blockIdx.x * blockDim.x + threadIdx.x;
    if (i >= total) return;
    const int n = (int)(i % N1_);
    const int c = (int)((i / N1_) % C2_);
    const int b = (int)(i / ((size_t)N1_ * C2_));
    const size_t kb = ((size_t)b * N1_ + n) * KNN_;
    const int   j0 = g_idx[kb+0], j1 = g_idx[kb+1], j2 = g_idx[kb+2];
    const float w0 = g_w[kb+0],  w1 = g_w[kb+1],  w2 = g_w[kb+2];
    const float* p = points2 + ((size_t)b * C2_ + c) * N2_;
    g_interp[i] = w0*p[j0] + w1*p[j1] + w2*p[j2];
}

// ---------------- kernel 3: FFMA2 SGEMM (+bias, optional BN+ReLU on input) ---
// Y[b,m,n] = sum_k W[m,k] * X[b,k,n] + bias[m]
// Tile: 128m x 256n x 8k, 256 threads, 8x16 microtile, double-buffered smem.
// If BN_IN: X is transformed as relu(scale[k]*x + shift[k]) on load.
template<bool BN_IN>
__global__ void __launch_bounds__(256) gemm_kernel(
    const float* __restrict__ Wm, int Mdim, int Kdim,
    const float* __restrict__ XA, int KA,
    const float* __restrict__ XB,
    const float* __restrict__ bias,
    const float* __restrict__ bn_scale,
    const float* __restrict__ bn_shift,
    float* __restrict__ Y)
{
    __shared__ float As[2][8][128];
    __shared__ float Bs[2][8][256];

    const int b  = blockIdx.z;
    const int n0 = blockIdx.x * 256;
    const int m0 = blockIdx.y * 128;
    const int tid = threadIdx.x;
    const int tn = tid & 15;        // 16 threads cover n (4 floats x 4 strided chunks)
    const int tm = tid >> 4;        // 16 threads cover m (8 rows each)

    const float* Abat = XA + (size_t)b * KA * N1_;
    const float* Bbat = XB + (size_t)b * (size_t)(Kdim - KA) * N1_;

    const int wr = tid >> 1;        // W row   0..127
    const int wk = (tid & 1) * 4;   // W k-col 0 or 4
    const int xr = tid >> 5;        // X k-row 0..7
    const int xc = (tid & 31) * 4;  // X n-col base (plus +128 for 2nd float4)

    ull acc[8][8];
    #pragma unroll
    for (int i = 0; i < 8; i++)
        #pragma unroll
        for (int j = 0; j < 8; j++) acc[i][j] = 0ull;

    float4 wv, xv0, xv1;

    auto ld_tile = [&](int kt) {
        wv = *(const float4*)(Wm + (size_t)(m0 + wr) * Kdim + kt + wk);
        const int k = kt + xr;
        const float* src = (k < KA) ? (Abat + (size_t)k * N1_)
                                    : (Bbat + (size_t)(k - KA) * N1_);
        const float* p = src + n0 + xc;
        xv0 = *(const float4*)p;
        xv1 = *(const float4*)(p + 128);
        if (BN_IN) {
            const float sc = bn_scale[k], so = bn_shift[k];
            xv0.x = fmaxf(fmaf(sc, xv0.x, so), 0.f);
            xv0.y = fmaxf(fmaf(sc, xv0.y, so), 0.f);
            xv0.z = fmaxf(fmaf(sc, xv0.z, so), 0.f);
            xv0.w = fmaxf(fmaf(sc, xv0.w, so), 0.f);
            xv1.x = fmaxf(fmaf(sc, xv1.x, so), 0.f);
            xv1.y = fmaxf(fmaf(sc, xv1.y, so), 0.f);
            xv1.z = fmaxf(fmaf(sc, xv1.z, so), 0.f);
            xv1.w = fmaxf(fmaf(sc, xv1.w, so), 0.f);
        }
    };
    auto st_tile = [&](int buf) {
        As[buf][wk+0][wr] = wv.x; As[buf][wk+1][wr] = wv.y;
        As[buf][wk+2][wr] = wv.z; As[buf][wk+3][wr] = wv.w;
        *(float4*)&Bs[buf][xr][xc]       = xv0;
        *(float4*)&Bs[buf][xr][xc + 128] = xv1;
    };

    ld_tile(0);
    st_tile(0);
    __syncthreads();

    const int ntiles = Kdim / 8;
    for (int t = 0; t < ntiles; t++) {
        const int cur = t & 1;
        const bool has_next = (t + 1 < ntiles);
        if (has_next) ld_tile((t + 1) * 8);

        #pragma unroll
        for (int kk = 0; kk < 8; kk++) {
            float a[8];
            *(float4*)(a)     = *(const float4*)&As[cur][kk][tm*8];
            *(float4*)(a + 4) = *(const float4*)&As[cur][kk][tm*8 + 4];
            ull b2[8];
            const float* brow = &Bs[cur][kk][0];
            #pragma unroll
            for (int q = 0; q < 4; q++) {
                ulonglong2 v = *(const ulonglong2*)(brow + tn*4 + 64*q);
                b2[2*q]   = v.x;
                b2[2*q+1] = v.y;
            }
            #pragma unroll
            for (int i = 0; i < 8; i++) {
                const ull a2 = pack2(a[i], a[i]);
                #pragma unroll
                for (int j = 0; j < 8; j++) fma2(acc[i][j], a2, b2[j]);
            }
        }

        if (has_next) {
            st_tile((t + 1) & 1);
            __syncthreads();
        }
    }

    #pragma unroll
    for (int i = 0; i < 8; i++) {
        const int m = m0 + tm*8 + i;
        const float bv = bias[m];
        const ull bb = pack2(bv, bv);
        float* dst = Y + ((size_t)b * Mdim + m) * N1_ + n0;
        #pragma unroll
        for (int q = 0; q < 4; q++) {
            float4 o;
            unpack2(add2(acc[i][2*q],   bb), o.x, o.y);
            unpack2(add2(acc[i][2*q+1], bb), o.z, o.w);
            *(float4*)(dst + tn*4 + 64*q) = o;
        }
    }
}

// ---------------- kernel 4a: partial per-channel sums ------------------------
__global__ void __launch_bounds__(256) stats_part_kernel(const float* __restrict__ Yv, int Mdim)
{
    const int c = blockIdx.x;
    const int s = blockIdx.y;     // batch slice: batches 2s, 2s+1
    float sum = 0.0f, sum2 = 0.0f;
    #pragma unroll
    for (int bo = 0; bo < 2; bo++) {
        const float* p = Yv + ((size_t)(2*s + bo) * Mdim + c) * N1_;
        for (int n = threadIdx.x * 4; n < N1_; n += 1024) {
            float4 v = *(const float4*)(p + n);
            sum  += v.x + v.y + v.z + v.w;
            sum2 += v.x*v.x + v.y*v.y + v.z*v.z + v.w*v.w;
        }
    }
    __shared__ float sh[256], sh2[256];
    sh[threadIdx.x] = sum; sh2[threadIdx.x] = sum2;
    __syncthreads();
    for (int o = 128; o > 0; o >>= 1) {
        if (threadIdx.x < o) {
            sh[threadIdx.x]  += sh[threadIdx.x + o];
            sh2[threadIdx.x] += sh2[threadIdx.x + o];
        }
        __syncthreads();
    }
    if (threadIdx.x == 0) {
        g_psum [c*8 + s] = sh[0];
        g_psum2[c*8 + s] = sh2[0];
    }
}

// ---------------- kernel 4b: finalize scale/shift -----------------------------
__global__ void __launch_bounds__(256) stats_final_kernel(const float* __restrict__ gamma,
                                                          const float* __restrict__ beta,
                                                          int Mdim, int layer)
{
    const int c = threadIdx.x;
    if (c >= Mdim) return;
    float s = 0.0f, s2 = 0.0f;
    #pragma unroll
    for (int i = 0; i < 8; i++) { s += g_psum[c*8+i]; s2 += g_psum2[c*8+i]; }
    const float cnt = (float)(Bb_ * N1_);
    float m = s / cnt;
    float v = s2 / cnt - m * m;
    float r = rsqrtf(v + BNEPS);
    float a = gamma[c] * r;
    if (layer == 0) { g_scale0[c] = a; g_shift0[c] = beta[c] - a * m; }
    else            { g_scale1[c] = a; g_shift1[c] = beta[c] - a * m; }
}

// ---------------- kernel 5: fused BN + ReLU (final layer, in place) ----------
__global__ void __launch_bounds__(256) bnrelu_kernel(float* __restrict__ Yv, int Mdim)
{
    const size_t total4 = (size_t)Bb_ * Mdim * N1_ / 4;
    const size_t i = (size_t)blockIdx.x * blockDim.x + threadIdx.x;
    if (i >= total4) return;
    const int c = (int)((i >> 10) % Mdim);
    const float a  = g_scale1[c];
    const float sh = g_shift1[c];
    float4 v = ((float4*)Yv)[i];
    v.x = fmaxf(fmaf(a, v.x, sh), 0.0f);
    v.y = fmaxf(fmaf(a, v.y, sh), 0.0f);
    v.z = fmaxf(fmaf(a, v.z, sh), 0.0f);
    v.w = fmaxf(fmaf(a, v.w, sh), 0.0f);
    ((float4*)Yv)[i] = v;
}

// ---------------- launch ------------------------------------------------------
extern "C" void kernel_launch(void* const* d_in, const int* in_sizes, int n_in,
                              void* d_out, int out_size)
{
    const float* xyz1    = (const float*)d_in[0];
    const float* xyz2    = (const float*)d_in[1];
    const float* points1 = (const float*)d_in[2];
    const float* points2 = (const float*)d_in[3];
    const float* W0 = (const float*)d_in[4];
    const float* b0 = (const float*)d_in[5];
    const float* g0 = (const float*)d_in[6];
    const float* be0= (const float*)d_in[7];
    const float* W1 = (const float*)d_in[8];
    const float* b1 = (const float*)d_in[9];
    const float* g1 = (const float*)d_in[10];
    const float* be1= (const float*)d_in[11];
    float* out = (float*)d_out;

    void* p_interp; cudaGetSymbolAddress(&p_interp, g_interp);
    void* p_y0;     cudaGetSymbolAddress(&p_y0, g_y0);
    void* p_s0;     cudaGetSymbolAddress(&p_s0, g_scale0);
    void* p_h0;     cudaGetSymbolAddress(&p_h0, g_shift0);
    float* interp = (float*)p_interp;
    float* y0     = (float*)p_y0;
    float* sc0    = (float*)p_s0;
    float* sh0    = (float*)p_h0;

    // 1. 3-NN
    knn_kernel<<<dim3(N1_/128, Bb_), 128>>>(xyz1, xyz2);

    // 2. interpolation
    {
        size_t total = (size_t)Bb_ * C2_ * N1_;
        interp_kernel<<<(unsigned)((total + 255) / 256), 256>>>(points2);
    }

    // 3. GEMM0: [256 x 384] @ [384 x N] + b0 -> y0 (raw, pre-BN)
    gemm_kernel<false><<<dim3(N1_/256, M0_/128, Bb_), 256>>>(
        W0, M0_, K0_, points1, C1_, interp, b0, nullptr, nullptr, y0);

    // 4. BN0 stats (two-stage, deterministic)
    stats_part_kernel<<<dim3(M0_, 8), 256>>>(y0, M0_);
    stats_final_kernel<<<1, 256>>>(g0, be0, M0_, 0);

    // 5. GEMM1 with BN0+ReLU fused into input load: [128 x 256] @ [256 x N] + b1 -> out
    gemm_kernel<true><<<dim3(N1_/256, M1_/128, Bb_), 256>>>(
        W1, M1_, M0_, y0, M0_, y0, b1, sc0, sh0, out);

    // 6. BN1 stats
    stats_part_kernel<<<dim3(M1_, 8), 256>>>(out, M1_);
    stats_final_kernel<<<1, 256>>>(g1, be1, M1_, 1);

    // 7. BN1 + ReLU in place on out
    {
        size_t total4 = (size_t)Bb_ * M1_ * N1_ / 4;
        bnrelu_kernel<<<(unsigned)((total4 + 255) / 256), 256>>>(out, M1_);
    }
}

// round 5
// speedup vs baseline: 1.8357x; 1.7336x over previous
#include <cuda_runtime.h>
#include <cuda_bf16.h>
#include <cstdint>

#define Bb_  16
#define N1_  4096
#define N2_  1024
#define C1_  128
#define C2_  256
#define K0_  384
#define M0_  256
#define M1_  128
#define KNN_ 3
#define EPSD 1e-10f
#define BNEPS 1e-5f

// GEMM tiling
#define BM 128
#define BN 128
#define BK 32
#define A_STRIDE 80u      // bytes per A smem row (32 bf16 + pad)
#define B_STRIDE 272u     // bytes per B smem row (128 bf16 + pad)
#define SZ_A (128u*A_STRIDE)          // 10240
#define SZ_B (32u*B_STRIDE)           // 8704
#define OFF_AL (SZ_A)
#define OFF_BH (2u*SZ_A)              // 20480
#define OFF_BL (2u*SZ_A + SZ_B)       // 29184
#define BUF_SZ (2u*SZ_A + 2u*SZ_B)    // 37888
#define SMEM_GEMM (2u*BUF_SZ)         // 75776

// ---------------- scratch ----------------------------------------------------
__device__ int   g_idx[Bb_ * N1_ * KNN_];
__device__ float g_w  [Bb_ * N1_ * KNN_];
__device__ float g_interp[(size_t)Bb_ * C2_ * N1_];
__device__ float g_y0    [(size_t)Bb_ * M0_ * N1_];
__device__ float g_psum [M0_ * 8];
__device__ float g_psum2[M0_ * 8];
__device__ float g_scale0[M0_], g_shift0[M0_];
__device__ float g_scale1[M1_], g_shift1[M1_];
__device__ __nv_bfloat16 g_w0h[M0_ * K0_], g_w0l[M0_ * K0_];
__device__ __nv_bfloat16 g_w1h[M1_ * M0_], g_w1l[M1_ * M0_];

// ---------------- warp-MMA helpers (baseline PTX, sm_80+) --------------------
__device__ __forceinline__ uint32_t smem_u32(const void* p) {
    uint32_t a;
    asm("{ .reg .u64 t; cvta.to.shared.u64 t, %1; cvt.u32.u64 %0, t; }" : "=r"(a) : "l"(p));
    return a;
}
__device__ __forceinline__ void ldsm_x4(uint32_t* r, uint32_t addr) {
    asm volatile("ldmatrix.sync.aligned.m8n8.x4.shared.b16 {%0,%1,%2,%3}, [%4];"
                 : "=r"(r[0]), "=r"(r[1]), "=r"(r[2]), "=r"(r[3]) : "r"(addr));
}
__device__ __forceinline__ void ldsm_x4t(uint32_t* r, uint32_t addr) {
    asm volatile("ldmatrix.sync.aligned.m8n8.x4.trans.shared.b16 {%0,%1,%2,%3}, [%4];"
                 : "=r"(r[0]), "=r"(r[1]), "=r"(r[2]), "=r"(r[3]) : "r"(addr));
}
__device__ __forceinline__ void mma_bf16(float* d, const uint32_t* a, const uint32_t* b) {
    asm volatile("mma.sync.aligned.m16n8k16.row.col.f32.bf16.bf16.f32 "
                 "{%0,%1,%2,%3}, {%4,%5,%6,%7}, {%8,%9}, {%0,%1,%2,%3};"
                 : "+f"(d[0]), "+f"(d[1]), "+f"(d[2]), "+f"(d[3])
                 : "r"(a[0]), "r"(a[1]), "r"(a[2]), "r"(a[3]), "r"(b[0]), "r"(b[1]));
}
__device__ __forceinline__ uint32_t pack_bf16x2(float lo, float hi) {
    __nv_bfloat16 h0 = __float2bfloat16_rn(lo);
    __nv_bfloat16 h1 = __float2bfloat16_rn(hi);
    return (uint32_t)__bfloat16_as_ushort(h0) | ((uint32_t)__bfloat16_as_ushort(h1) << 16);
}

// ---------------- kernel 1: 3-NN + inverse-distance weights -----------------
__global__ void __launch_bounds__(128) knn_kernel(const float* __restrict__ xyz1,
                                                  const float* __restrict__ xyz2)
{
    __shared__ float sx[N2_], sy[N2_], sz[N2_], ss[N2_];
    const int b = blockIdx.y;
    const float* p2 = xyz2 + (size_t)b * N2_ * 3;
    for (int j = threadIdx.x; j < N2_; j += blockDim.x) {
        float x = p2[j*3+0], y = p2[j*3+1], z = p2[j*3+2];
        sx[j] = x; sy[j] = y; sz[j] = z; ss[j] = x*x + y*y + z*z;
    }
    __syncthreads();

    const int n = blockIdx.x * blockDim.x + threadIdx.x;
    const float* p1 = xyz1 + ((size_t)b * N1_ + n) * 3;
    const float x1 = p1[0], y1 = p1[1], z1 = p1[2];
    const float s1 = x1*x1 + y1*y1 + z1*z1;

    float d0 = 3.0e38f, d1 = 3.0e38f, d2 = 3.0e38f;
    int   i0 = 0, i1 = 0, i2 = 0;
    #pragma unroll 4
    for (int j = 0; j < N2_; j++) {
        float d = s1 + ss[j] - 2.0f * (x1*sx[j] + y1*sy[j] + z1*sz[j]);
        d = fmaxf(d, EPSD);
        if (d < d2) {
            if (d < d1) {
                d2 = d1; i2 = i1;
                if (d < d0) { d1 = d0; i1 = i0; d0 = d; i0 = j; }
                else        { d1 = d;  i1 = j; }
            } else { d2 = d; i2 = j; }
        }
    }
    float w0 = 1.0f/d0, w1 = 1.0f/d1, w2 = 1.0f/d2;
    float inv = 1.0f / (w0 + w1 + w2);
    size_t base = ((size_t)b * N1_ + n) * KNN_;
    g_idx[base+0] = i0; g_idx[base+1] = i1; g_idx[base+2] = i2;
    g_w  [base+0] = w0*inv; g_w[base+1] = w1*inv; g_w[base+2] = w2*inv;
}

// ---------------- kernel 2: interpolate (idx/w hoisted, coalesced stores) ----
__global__ void __launch_bounds__(256) interp_kernel(const float* __restrict__ points2)
{
    const int b = blockIdx.y;
    const int n = blockIdx.x * 256 + threadIdx.x;
    const size_t kb = ((size_t)b * N1_ + n) * KNN_;
    const int   j0 = g_idx[kb+0], j1 = g_idx[kb+1], j2 = g_idx[kb+2];
    const float w0 = g_w[kb+0],  w1 = g_w[kb+1],  w2 = g_w[kb+2];
    const float* p = points2 + (size_t)b * C2_ * N2_;
    float* dst = g_interp + (size_t)b * C2_ * N1_ + n;
    #pragma unroll 4
    for (int c = 0; c < C2_; c++) {
        const float* row = p + (size_t)c * N2_;
        dst[(size_t)c * N1_] = w0*row[j0] + w1*row[j1] + w2*row[j2];
    }
}

// ---------------- kernel 2b: split weights fp32 -> bf16 hi/lo ----------------
__global__ void __launch_bounds__(256) splitw_kernel(const float* __restrict__ W0,
                                                     const float* __restrict__ W1)
{
    const int i = blockIdx.x * 256 + threadIdx.x;
    if (i < M0_ * K0_) {
        float v = W0[i];
        __nv_bfloat16 h = __float2bfloat16_rn(v);
        g_w0h[i] = h;
        g_w0l[i] = __float2bfloat16_rn(v - __bfloat162float(h));
    }
    if (i < M1_ * M0_) {
        float v = W1[i];
        __nv_bfloat16 h = __float2bfloat16_rn(v);
        g_w1h[i] = h;
        g_w1l[i] = __float2bfloat16_rn(v - __bfloat162float(h));
    }
}

// ---------------- kernel 3: split-bf16 mma.sync GEMM -------------------------
// Y[b,m,n] = sum_k W[m,k]*X[b,k,n] + bias[m];  D = Ah*Bh + Al*Bh + Ah*Bl
// CTA: 128m x 128n x 32k double-buffered; 8 warps of 64m x 32n.
__global__ void __launch_bounds__(256, 1) mma_gemm(
    const __nv_bfloat16* __restrict__ Wh, const __nv_bfloat16* __restrict__ Wl,
    int Mdim, int Kdim,
    const float* __restrict__ XA, int KA,
    const float* __restrict__ XB,
    const float* __restrict__ bias,
    const float* __restrict__ bnsc, const float* __restrict__ bnsh, int bn_in,
    float* __restrict__ Y)
{
    extern __shared__ __align__(16) char sm[];
    const uint32_t sbase = smem_u32(sm);

    const int tid = threadIdx.x;
    const int lane = tid & 31, wid = tid >> 5;
    const int wm = wid >> 2, wn = wid & 3;          // warp grid 2m x 4n
    const int bb = blockIdx.z;
    const int m0 = blockIdx.y * BM;
    const int n0 = blockIdx.x * BN;

    const float* XAb = XA + (size_t)bb * KA * N1_;
    const float* XBb = XB + (size_t)bb * (size_t)(Kdim - KA) * N1_;

    // staging indices
    const int am   = tid >> 1;          // A row 0..127
    const int ak16 = (tid & 1) * 16;    // A col group (bf16)
    const int bk   = tid >> 3;          // B row 0..31
    const int bn16 = (tid & 7) * 16;    // B col group (floats)

    uint4 wva[2][2];      // prefetched A: [h/l][2 x uint4]
    float xf[16];         // prefetched B row chunk (fp32, post-BN)

    auto ldA = [&](int kt) {
        const __nv_bfloat16* sh_ = Wh + (size_t)(m0 + am) * Kdim + kt + ak16;
        const __nv_bfloat16* sl_ = Wl + (size_t)(m0 + am) * Kdim + kt + ak16;
        wva[0][0] = *(const uint4*)(sh_);     wva[0][1] = *(const uint4*)(sh_ + 8);
        wva[1][0] = *(const uint4*)(sl_);     wva[1][1] = *(const uint4*)(sl_ + 8);
    };
    auto ldB = [&](int kt) {
        const int k = kt + bk;
        const float* src = (k < KA) ? (XAb + (size_t)k * N1_)
                                    : (XBb + (size_t)(k - KA) * N1_);
        const float* p = src + n0 + bn16;
        *(float4*)(xf)      = *(const float4*)(p);
        *(float4*)(xf + 4)  = *(const float4*)(p + 4);
        *(float4*)(xf + 8)  = *(const float4*)(p + 8);
        *(float4*)(xf + 12) = *(const float4*)(p + 12);
        if (bn_in) {
            const float sc = bnsc[k], so = bnsh[k];
            #pragma unroll
            for (int q = 0; q < 16; q++) xf[q] = fmaxf(fmaf(sc, xf[q], so), 0.0f);
        }
    };
    auto stA = [&](char* buf) {
        char* ah = buf + (size_t)am * A_STRIDE + ak16 * 2;
        *(uint4*)(ah)                 = wva[0][0];
        *(uint4*)(ah + 16)            = wva[0][1];
        *(uint4*)(ah + OFF_AL)        = wva[1][0];
        *(uint4*)(ah + OFF_AL + 16)   = wva[1][1];
    };
    auto stB = [&](char* buf) {
        uint32_t h[8], l[8];
        #pragma unroll
        for (int q = 0; q < 8; q++) {
            float x0 = xf[2*q], x1 = xf[2*q+1];
            __nv_bfloat16 h0 = __float2bfloat16_rn(x0);
            __nv_bfloat16 h1 = __float2bfloat16_rn(x1);
            float r0 = x0 - __bfloat162float(h0);
            float r1 = x1 - __bfloat162float(h1);
            h[q] = (uint32_t)__bfloat16_as_ushort(h0) | ((uint32_t)__bfloat16_as_ushort(h1) << 16);
            l[q] = pack_bf16x2(r0, r1);
        }
        char* bh = buf + OFF_BH + (size_t)bk * B_STRIDE + bn16 * 2;
        *(uint4*)(bh)      = make_uint4(h[0], h[1], h[2], h[3]);
        *(uint4*)(bh + 16) = make_uint4(h[4], h[5], h[6], h[7]);
        char* bl = bh + (OFF_BL - OFF_BH);
        *(uint4*)(bl)      = make_uint4(l[0], l[1], l[2], l[3]);
        *(uint4*)(bl + 16) = make_uint4(l[4], l[5], l[6], l[7]);
    };

    float acc[4][4][4];
    #pragma unroll
    for (int i = 0; i < 4; i++)
        #pragma unroll
        for (int j = 0; j < 4; j++)
            #pragma unroll
            for (int q = 0; q < 4; q++) acc[i][j][q] = 0.0f;

    // ldmatrix address components (per buffer, add buffer base)
    const uint32_t a_row = (uint32_t)(wm*64 + (lane & 15));  // + i*16 rows
    const uint32_t a_col = (uint32_t)((lane >> 4) * 8) * 2;  // + kh*32 bytes
    const uint32_t b_colbase = (uint32_t)(wn*32 + (lane >> 4) * 8) * 2;   // + j2*32 bytes
    const uint32_t b_row = (uint32_t)(lane & 15);            // + kh*16 rows

    ldA(0); ldB(0);
    stA(sm); stB(sm);
    __syncthreads();

    const int T = Kdim / BK;
    for (int t = 0; t < T; t++) {
        char* cbuf = sm + (size_t)(t & 1) * BUF_SZ;
        const uint32_t cb = sbase + (uint32_t)(t & 1) * BUF_SZ;
        if (t + 1 < T) { ldA((t+1)*BK); ldB((t+1)*BK); }

        #pragma unroll
        for (int kh = 0; kh < 2; kh++) {
            uint32_t ah[4][4], al[4][4];
            #pragma unroll
            for (int i = 0; i < 4; i++) {
                uint32_t addr = cb + (a_row + i*16) * A_STRIDE + a_col + kh*32;
                ldsm_x4(ah[i], addr);
                ldsm_x4(al[i], addr + OFF_AL);
            }
            uint32_t bh[4][2], bl[4][2];
            #pragma unroll
            for (int j2 = 0; j2 < 2; j2++) {
                uint32_t addr = cb + OFF_BH + (b_row + kh*16) * B_STRIDE + b_colbase + j2*32;
                uint32_t r[4];
                ldsm_x4t(r, addr);
                bh[2*j2][0] = r[0]; bh[2*j2][1] = r[1];
                bh[2*j2+1][0] = r[2]; bh[2*j2+1][1] = r[3];
                ldsm_x4t(r, addr + (OFF_BL - OFF_BH));
                bl[2*j2][0] = r[0]; bl[2*j2][1] = r[1];
                bl[2*j2+1][0] = r[2]; bl[2*j2+1][1] = r[3];
            }
            #pragma unroll
            for (int i = 0; i < 4; i++)
                #pragma unroll
                for (int j = 0; j < 4; j++) {
                    mma_bf16(acc[i][j], ah[i], bh[j]);
                    mma_bf16(acc[i][j], al[i], bh[j]);
                    mma_bf16(acc[i][j], ah[i], bl[j]);
                }
        }

        if (t + 1 < T) {
            char* nbuf = sm + (size_t)((t+1) & 1) * BUF_SZ;
            stA(nbuf); stB(nbuf);
        }
        __syncthreads();
    }

    // epilogue: bias add + store fp32
    #pragma unroll
    for (int i = 0; i < 4; i++) {
        const int r0 = m0 + wm*64 + i*16 + (lane >> 2);
        const int r1 = r0 + 8;
        const float bv0 = bias[r0], bv1 = bias[r1];
        float* y0p = Y + ((size_t)bb * Mdim + r0) * N1_ + n0 + wn*32;
        float* y1p = Y + ((size_t)bb * Mdim + r1) * N1_ + n0 + wn*32;
        #pragma unroll
        for (int j = 0; j < 4; j++) {
            const int nc = j*8 + (lane & 3)*2;
            *(float2*)(y0p + nc) = make_float2(acc[i][j][0] + bv0, acc[i][j][1] + bv0);
            *(float2*)(y1p + nc) = make_float2(acc[i][j][2] + bv1, acc[i][j][3] + bv1);
        }
    }
}

// ---------------- kernel 4a: partial per-channel sums ------------------------
__global__ void __launch_bounds__(256) stats_part_kernel(const float* __restrict__ Yv, int Mdim)
{
    const int c = blockIdx.x;
    const int s = blockIdx.y;
    float sum = 0.0f, sum2 = 0.0f;
    #pragma unroll
    for (int bo = 0; bo < 2; bo++) {
        const float* p = Yv + ((size_t)(2*s + bo) * Mdim + c) * N1_;
        for (int n = threadIdx.x * 4; n < N1_; n += 1024) {
            float4 v = *(const float4*)(p + n);
            sum  += v.x + v.y + v.z + v.w;
            sum2 += v.x*v.x + v.y*v.y + v.z*v.z + v.w*v.w;
        }
    }
    __shared__ float sh[256], sh2[256];
    sh[threadIdx.x] = sum; sh2[threadIdx.x] = sum2;
    __syncthreads();
    for (int o = 128; o > 0; o >>= 1) {
        if (threadIdx.x < o) {
            sh[threadIdx.x]  += sh[threadIdx.x + o];
            sh2[threadIdx.x] += sh2[threadIdx.x + o];
        }
        __syncthreads();
    }
    if (threadIdx.x == 0) {
        g_psum [c*8 + s] = sh[0];
        g_psum2[c*8 + s] = sh2[0];
    }
}

// ---------------- kernel 4b: finalize scale/shift ----------------------------
__global__ void __launch_bounds__(256) stats_final_kernel(const float* __restrict__ gamma,
                                                          const float* __restrict__ beta,
                                                          int Mdim, int layer)
{
    const int c = threadIdx.x;
    if (c >= Mdim) return;
    float s = 0.0f, s2 = 0.0f;
    #pragma unroll
    for (int i = 0; i < 8; i++) { s += g_psum[c*8+i]; s2 += g_psum2[c*8+i]; }
    const float cnt = (float)(Bb_ * N1_);
    float m = s / cnt;
    float v = s2 / cnt - m * m;
    float r = rsqrtf(v + BNEPS);
    float a = gamma[c] * r;
    if (layer == 0) { g_scale0[c] = a; g_shift0[c] = beta[c] - a * m; }
    else            { g_scale1[c] = a; g_shift1[c] = beta[c] - a * m; }
}

// ---------------- kernel 5: fused BN + ReLU (final layer, in place) ----------
__global__ void __launch_bounds__(256) bnrelu_kernel(float* __restrict__ Yv, int Mdim)
{
    const size_t total4 = (size_t)Bb_ * Mdim * N1_ / 4;
    const size_t i = (size_t)blockIdx.x * blockDim.x + threadIdx.x;
    if (i >= total4) return;
    const int c = (int)((i >> 10) % Mdim);
    const float a  = g_scale1[c];
    const float sh = g_shift1[c];
    float4 v = ((float4*)Yv)[i];
    v.x = fmaxf(fmaf(a, v.x, sh), 0.0f);
    v.y = fmaxf(fmaf(a, v.y, sh), 0.0f);
    v.z = fmaxf(fmaf(a, v.z, sh), 0.0f);
    v.w = fmaxf(fmaf(a, v.w, sh), 0.0f);
    ((float4*)Yv)[i] = v;
}

// ---------------- launch ------------------------------------------------------
extern "C" void kernel_launch(void* const* d_in, const int* in_sizes, int n_in,
                              void* d_out, int out_size)
{
    const float* xyz1    = (const float*)d_in[0];
    const float* xyz2    = (const float*)d_in[1];
    const float* points1 = (const float*)d_in[2];
    const float* points2 = (const float*)d_in[3];
    const float* W0 = (const float*)d_in[4];
    const float* b0 = (const float*)d_in[5];
    const float* g0 = (const float*)d_in[6];
    const float* be0= (const float*)d_in[7];
    const float* W1 = (const float*)d_in[8];
    const float* b1 = (const float*)d_in[9];
    const float* g1 = (const float*)d_in[10];
    const float* be1= (const float*)d_in[11];
    float* out = (float*)d_out;

    void* p;
    cudaGetSymbolAddress(&p, g_interp);  float* interp = (float*)p;
    cudaGetSymbolAddress(&p, g_y0);      float* y0     = (float*)p;
    cudaGetSymbolAddress(&p, g_scale0);  float* sc0    = (float*)p;
    cudaGetSymbolAddress(&p, g_shift0);  float* sh0    = (float*)p;
    cudaGetSymbolAddress(&p, g_w0h);     __nv_bfloat16* w0h = (__nv_bfloat16*)p;
    cudaGetSymbolAddress(&p, g_w0l);     __nv_bfloat16* w0l = (__nv_bfloat16*)p;
    cudaGetSymbolAddress(&p, g_w1h);     __nv_bfloat16* w1h = (__nv_bfloat16*)p;
    cudaGetSymbolAddress(&p, g_w1l);     __nv_bfloat16* w1l = (__nv_bfloat16*)p;

    cudaFuncSetAttribute(mma_gemm, cudaFuncAttributeMaxDynamicSharedMemorySize, SMEM_GEMM);

    // 0. split weights to bf16 hi/lo
    splitw_kernel<<<(M0_*K0_ + 255)/256, 256>>>(W0, W1);

    // 1. 3-NN
    knn_kernel<<<dim3(N1_/128, Bb_), 128>>>(xyz1, xyz2);

    // 2. interpolation
    interp_kernel<<<dim3(N1_/256, Bb_), 256>>>(points2);

    // 3. GEMM0: [256 x 384] @ [384 x N] + b0 -> y0
    mma_gemm<<<dim3(N1_/BN, M0_/BM, Bb_), 256, SMEM_GEMM>>>(
        w0h, w0l, M0_, K0_, points1, C1_, interp, b0, nullptr, nullptr, 0, y0);

    // 4. BN0 stats
    stats_part_kernel<<<dim3(M0_, 8), 256>>>(y0, M0_);
    stats_final_kernel<<<1, 256>>>(g0, be0, M0_, 0);

    // 5. GEMM1 with BN0+ReLU fused into staging: [128 x 256] @ [256 x N] + b1 -> out
    mma_gemm<<<dim3(N1_/BN, M1_/BM, Bb_), 256, SMEM_GEMM>>>(
        w1h, w1l, M1_, M0_, y0, M0_, y0, b1, sc0, sh0, 1, out);

    // 6. BN1 stats
    stats_part_kernel<<<dim3(M1_, 8), 256>>>(out, M1_);
    stats_final_kernel<<<1, 256>>>(g1, be1, M1_, 1);

    // 7. BN1 + ReLU in place on out
    {
        size_t total4 = (size_t)Bb_ * M1_ * N1_ / 4;
        bnrelu_kernel<<<(unsigned)((total4 + 255) / 256), 256>>>(out, M1_);
    }
}